// round 13
// baseline (speedup 1.0000x reference)
#include <cuda_runtime.h>
#include <cstdint>
#include <cstddef>

// Problem shape (fixed by the reference setup_inputs): B=4, H=16, L=1024, D=64
constexpr int Lc = 1024;
constexpr int Dc = 64;
constexpr int NBH  = 64;             // B*H
constexpr int NCOL = NBH * Dc;       // 4096 (bh, d) columns

constexpr int THREADS = 256;
constexpr int RPB = 8;               // rows per block in rows_kernel

// Transposed copies: [bh][d][L] so each sort block reads a contiguous column.
__device__ float g_qT[(size_t)NCOL * Lc];
__device__ float g_kT[(size_t)NCOL * Lc];

// Stage: for each (bh, qi-row, d) exactly one packed {kj, val} pair (8B).
// ~33.5MB, largely L2-resident between kernels B and C. No zero-init needed:
// every entry written exactly once (qi is a permutation per (bh,d) column).
__device__ uint2 g_stage[(size_t)NBH * Lc * Dc];

// ---------------------------------------------------------------------------
// Kernel A: transpose q,k into [bh][d][L]. 64MB DRAM, pure streaming.
// (measured 11.5us)
// ---------------------------------------------------------------------------
__global__ __launch_bounds__(THREADS)
void prep_kernel(const float* __restrict__ q,
                 const float* __restrict__ k)
{
    __shared__ float tile[32][33];

    const int bid = blockIdx.x;
    const int dt  = bid & 1;
    const int rt  = (bid >> 1) & 31;
    const int bh  = bid >> 6;

    const int x = threadIdx.x & 31;
    const int y = threadIdx.x >> 5;

    const int r0 = rt * 32;
    const int d0 = dt * 32;
    const size_t sbase = (size_t)bh * Lc * Dc;

#pragma unroll
    for (int i = 0; i < 4; i++) {
        int row = y + i * 8;
        tile[row][x] = q[sbase + (size_t)(r0 + row) * Dc + d0 + x];
    }
    __syncthreads();
#pragma unroll
    for (int i = 0; i < 4; i++) {
        int dr = y + i * 8;
        g_qT[((size_t)bh * Dc + d0 + dr) * Lc + r0 + x] = tile[x][dr];
    }
    __syncthreads();

#pragma unroll
    for (int i = 0; i < 4; i++) {
        int row = y + i * 8;
        tile[row][x] = k[sbase + (size_t)(r0 + row) * Dc + d0 + x];
    }
    __syncthreads();
#pragma unroll
    for (int i = 0; i < 4; i++) {
        int dr = y + i * 8;
        g_kT[((size_t)bh * Dc + d0 + dr) * Lc + r0 + x] = tile[x][dr];
    }
}

// ---------------------------------------------------------------------------
// Kernel B: one block per (bh, d). Distribution (counting) sort per column
// (exact: within-bucket lexicographic fixup), then emit the matched-rank
// packed {kj, val} to stage[bh][qi][d] with a SINGLE 8B store.
// No mask reads, no global atomics.
// ---------------------------------------------------------------------------
__global__ __launch_bounds__(THREADS)
void sort_stage_kernel()
{
    __shared__ float          qv[Lc];
    __shared__ unsigned short qi[Lc];
    __shared__ float          wval[Lc];
    __shared__ unsigned short widx[Lc];
    __shared__ unsigned short wbkt[Lc];
    __shared__ int            cursor[Lc];   // histogram, then scatter cursor
    __shared__ int            P0[Lc + 1];   // exclusive prefix (run bounds)
    __shared__ int            wtot[8];

    const int bid  = blockIdx.x;           // == bh*64 + d
    const int bh   = bid >> 6;
    const int d    = bid & (Dc - 1);
    const int t    = threadIdx.x;
    const int lane = t & 31;
    const int w    = t >> 5;

    constexpr float inv_D = 1.0f / (float)Dc;
    const size_t stage_bh = (size_t)bh * Lc * Dc;

    for (int phase = 0; phase < 2; phase++) {
        const float* col = (phase == 0 ? g_qT : g_kT) + (size_t)bid * Lc;

        // ---- load 4 values, compute buckets ----
        float4 v4 = reinterpret_cast<const float4*>(col)[t];
        float v[4] = {v4.x, v4.y, v4.z, v4.w};
        int   b[4];
#pragma unroll
        for (int i = 0; i < 4; i++) {
            float u = 0.5f * erff(v[i] * 0.70710678f) + 0.5f;
            int bi = (int)(u * 1024.0f);
            b[i] = bi < 0 ? 0 : (bi > 1023 ? 1023 : bi);
        }

        // ---- histogram ----
#pragma unroll
        for (int i = 0; i < 4; i++) cursor[t + THREADS * i] = 0;
        __syncthreads();
#pragma unroll
        for (int i = 0; i < 4; i++) atomicAdd(&cursor[b[i]], 1);
        __syncthreads();

        // ---- exclusive scan of 1024 bins (4 contiguous bins / thread) ----
        int c0 = cursor[4 * t + 0];
        int c1 = cursor[4 * t + 1];
        int c2 = cursor[4 * t + 2];
        int c3 = cursor[4 * t + 3];
        int s  = c0 + c1 + c2 + c3;
        int incl = s;
#pragma unroll
        for (int o = 1; o < 32; o <<= 1) {
            int n = __shfl_up_sync(0xFFFFFFFFu, incl, o);
            if (lane >= o) incl += n;
        }
        if (lane == 31) wtot[w] = incl;
        __syncthreads();
        if (t == 0) {
            int acc = 0;
#pragma unroll
            for (int i = 0; i < 8; i++) { int x = wtot[i]; wtot[i] = acc; acc += x; }
        }
        __syncthreads();
        int excl = wtot[w] + (incl - s);
        P0[4 * t + 0] = excl;
        P0[4 * t + 1] = excl + c0;
        P0[4 * t + 2] = excl + c0 + c1;
        P0[4 * t + 3] = excl + c0 + c1 + c2;
        cursor[4 * t + 0] = excl;
        cursor[4 * t + 1] = excl + c0;
        cursor[4 * t + 2] = excl + c0 + c1;
        cursor[4 * t + 3] = excl + c0 + c1 + c2;
        if (t == 0) P0[Lc] = Lc;
        __syncthreads();

        // ---- scatter into bucket-ordered arrays ----
#pragma unroll
        for (int i = 0; i < 4; i++) {
            int pos = atomicAdd(&cursor[b[i]], 1);
            wval[pos] = v[i];
            widx[pos] = (unsigned short)(4 * t + i);
            wbkt[pos] = (unsigned short)b[i];
        }
        __syncthreads();

        // ---- exact fixup: rank within bucket by (value, index) ----
#pragma unroll
        for (int i = 0; i < 4; i++) {
            int p = t + THREADS * i;
            float vv = wval[p];
            int   ii = widx[p];
            int   bb = wbkt[p];
            int start = P0[bb];
            int end   = P0[bb + 1];
            int r = p;                         // len==1 -> p == start
            if (end - start > 1) {
                r = start;
                for (int j = start; j < end; j++) {
                    float vj = wval[j];
                    if (vj < vv || (vj == vv && widx[j] < ii)) r++;
                }
            }
            if (phase == 0) {
                qv[r] = vv;
                qi[r] = (unsigned short)ii;
            } else {
                float dq  = qv[r] - vv;
                float val = __expf(-dq * dq) * inv_D;
                uint2 pk;
                pk.x = (unsigned)ii;                 // kj
                pk.y = __float_as_uint(val);
                g_stage[stage_bh + ((size_t)qi[r] << 6) + (unsigned)d] = pk;
            }
        }
        __syncthreads();   // qv/qi complete before k-phase; arrays reused
    }
}

// ---------------------------------------------------------------------------
// Kernel C: one block per 8 output rows of one bh. Coalesced uint2 stage
// reads, 2 independent mask probes per thread (latency hidden behind the
// 32KB smem zero-fill), smem atomics into the row buffer, then one coalesced
// 32KB row write. Replaces zero-write + global atomic RMW entirely.
// ---------------------------------------------------------------------------
__global__ __launch_bounds__(THREADS)
void rows_kernel(const int* __restrict__ mask,
                 float* __restrict__ out)
{
    __shared__ float rowbuf[RPB * Lc];     // 32KB: 8 rows

    const int bid  = blockIdx.x;           // 0 .. 8191
    const int bh   = bid >> 7;             // 128 blocks per bh
    const int row0 = (bid & 127) * RPB;
    const int t    = threadIdx.x;

    // stage entries for these 8 rows: 512 x uint2, coalesced (2 per thread)
    const size_t sbase = ((size_t)bh * Lc + row0) << 6;
    const uint2 e0 = g_stage[sbase + t];
    const uint2 e1 = g_stage[sbase + THREADS + t];

    const int row_a = t >> 6;              // 0..3
    const int row_b = 4 + row_a;           // 4..7

    // issue both mask probes now (independent, MLP=2); consumed after fill
    const int* mbase = mask + ((size_t)bh << 20) + ((size_t)row0 << 10);
    const int m0 = mbase[(row_a << 10) + (int)e0.x];
    const int m1 = mbase[(row_b << 10) + (int)e1.x];

    // zero the 8-row buffer (executes under the mask-load latency)
    {
        float4* rb = reinterpret_cast<float4*>(rowbuf);
        const float4 z4 = make_float4(0.f, 0.f, 0.f, 0.f);
#pragma unroll
        for (int i = 0; i < (RPB * Lc / 4) / THREADS; i++)
            rb[t + i * THREADS] = z4;
    }
    __syncthreads();

    if (m0 == 0) atomicAdd(&rowbuf[(row_a << 10) + (int)e0.x], __uint_as_float(e0.y));
    if (m1 == 0) atomicAdd(&rowbuf[(row_b << 10) + (int)e1.x], __uint_as_float(e1.y));
    __syncthreads();

    // write 8 full rows (32KB) coalesced
    float4* orow = reinterpret_cast<float4*>(
        out + ((size_t)bh << 20) + ((size_t)row0 << 10));
    const float4* src = reinterpret_cast<const float4*>(rowbuf);
#pragma unroll
    for (int i = 0; i < (RPB * Lc / 4) / THREADS; i++)
        orow[t + i * THREADS] = src[t + i * THREADS];
}

extern "C" void kernel_launch(void* const* d_in, const int* in_sizes, int n_in,
                              void* d_out, int out_size)
{
    const float* q    = (const float*)d_in[0];
    const float* k    = (const float*)d_in[1];
    const int*   mask = (const int*)d_in[2];
    float*       out  = (float*)d_out;

    prep_kernel<<<NCOL, THREADS>>>(q, k);
    sort_stage_kernel<<<NCOL, THREADS>>>();
    rows_kernel<<<NBH * (Lc / RPB), THREADS>>>(mask, out);
}

// round 14
// speedup vs baseline: 1.2354x; 1.2354x over previous
#include <cuda_runtime.h>
#include <cstdint>
#include <cstddef>

// Problem shape (fixed by the reference setup_inputs): B=4, H=16, L=1024, D=64
constexpr int Lc = 1024;
constexpr int Dc = 64;
constexpr int NBH  = 64;             // B*H
constexpr int NCOL = NBH * Dc;       // 4096 (bh, d) columns

constexpr int THREADS = 256;

// Transposed copies: [bh][d][L] so each sort block reads a contiguous column.
__device__ float g_qT[(size_t)NCOL * Lc];
__device__ float g_kT[(size_t)NCOL * Lc];

// ---------------------------------------------------------------------------
// Kernel A: transpose q,k into [bh][d][L] scratch AND zero the output.
// 384MB of DRAM traffic @ ~6.7TB/s measured — at the streaming cap.
// ---------------------------------------------------------------------------
__global__ __launch_bounds__(THREADS)
void prep_kernel(const float* __restrict__ q,
                 const float* __restrict__ k,
                 float* __restrict__ out)
{
    __shared__ float tile[32][33];

    const int bid = blockIdx.x;
    const int dt  = bid & 1;
    const int rt  = (bid >> 1) & 31;
    const int bh  = bid >> 6;

    const int x = threadIdx.x & 31;
    const int y = threadIdx.x >> 5;

    const int r0 = rt * 32;
    const int d0 = dt * 32;
    const size_t sbase = (size_t)bh * Lc * Dc;

    {   // zero my 64KB slice of out
        float4* oz = reinterpret_cast<float4*>(out) + (size_t)bid * 4096;
        const float4 z4 = make_float4(0.f, 0.f, 0.f, 0.f);
#pragma unroll
        for (int i = 0; i < 16; i++) oz[threadIdx.x + i * THREADS] = z4;
    }

#pragma unroll
    for (int i = 0; i < 4; i++) {
        int row = y + i * 8;
        tile[row][x] = q[sbase + (size_t)(r0 + row) * Dc + d0 + x];
    }
    __syncthreads();
#pragma unroll
    for (int i = 0; i < 4; i++) {
        int dr = y + i * 8;
        g_qT[((size_t)bh * Dc + d0 + dr) * Lc + r0 + x] = tile[x][dr];
    }
    __syncthreads();

#pragma unroll
    for (int i = 0; i < 4; i++) {
        int row = y + i * 8;
        tile[row][x] = k[sbase + (size_t)(r0 + row) * Dc + d0 + x];
    }
    __syncthreads();
#pragma unroll
    for (int i = 0; i < 4; i++) {
        int dr = y + i * 8;
        g_kT[((size_t)bh * Dc + d0 + dr) * Lc + r0 + x] = tile[x][dr];
    }
}

// ---------------------------------------------------------------------------
// Kernel B: one block per (bh, d). Distribution (counting) sort per column
// (exact: within-bucket lexicographic fixup), inline mask check + REDG
// scatter. The random-DRAM tail of each block hides under other blocks'
// compute-dense sort phases — this overlap is why the fused form wins.
// ---------------------------------------------------------------------------
__global__ __launch_bounds__(THREADS)
void sort_scatter_kernel(const int* __restrict__ mask,
                         float* __restrict__ out)
{
    __shared__ float          qv[Lc];
    __shared__ unsigned short qi[Lc];
    __shared__ float          wval[Lc];
    __shared__ unsigned short widx[Lc];
    __shared__ unsigned short wbkt[Lc];
    __shared__ int            cursor[Lc];   // histogram, then scatter cursor
    __shared__ int            P0[Lc + 1];   // exclusive prefix (run bounds)
    __shared__ int            wtot[8];

    const int bid  = blockIdx.x;           // == bh*64 + d
    const int bh   = bid >> 6;
    const int t    = threadIdx.x;
    const int lane = t & 31;
    const int w    = t >> 5;

    const int* mrow = mask + (size_t)bh * Lc * Lc;
    float*     orow = out  + (size_t)bh * Lc * Lc;
    constexpr float inv_D = 1.0f / (float)Dc;

    for (int phase = 0; phase < 2; phase++) {
        const float* col = (phase == 0 ? g_qT : g_kT) + (size_t)bid * Lc;

        // ---- load 4 values, compute buckets ----
        float4 v4 = reinterpret_cast<const float4*>(col)[t];
        float v[4] = {v4.x, v4.y, v4.z, v4.w};
        int   b[4];
#pragma unroll
        for (int i = 0; i < 4; i++) {
            float u = 0.5f * erff(v[i] * 0.70710678f) + 0.5f;
            int bi = (int)(u * 1024.0f);
            b[i] = bi < 0 ? 0 : (bi > 1023 ? 1023 : bi);
        }

        // ---- histogram ----
#pragma unroll
        for (int i = 0; i < 4; i++) cursor[t + THREADS * i] = 0;
        __syncthreads();
#pragma unroll
        for (int i = 0; i < 4; i++) atomicAdd(&cursor[b[i]], 1);
        __syncthreads();

        // ---- exclusive scan of 1024 bins (4 contiguous bins / thread) ----
        int c0 = cursor[4 * t + 0];
        int c1 = cursor[4 * t + 1];
        int c2 = cursor[4 * t + 2];
        int c3 = cursor[4 * t + 3];
        int s  = c0 + c1 + c2 + c3;
        int incl = s;
#pragma unroll
        for (int o = 1; o < 32; o <<= 1) {
            int n = __shfl_up_sync(0xFFFFFFFFu, incl, o);
            if (lane >= o) incl += n;
        }
        if (lane == 31) wtot[w] = incl;
        __syncthreads();
        // each thread folds the 8 warp totals itself (broadcast smem reads);
        // no second barrier, no serial thread-0 pass (validated in R11)
        int woff = 0;
#pragma unroll
        for (int i = 0; i < 8; i++) woff += (i < w) ? wtot[i] : 0;
        int excl = woff + (incl - s);
        P0[4 * t + 0] = excl;
        P0[4 * t + 1] = excl + c0;
        P0[4 * t + 2] = excl + c0 + c1;
        P0[4 * t + 3] = excl + c0 + c1 + c2;
        cursor[4 * t + 0] = excl;
        cursor[4 * t + 1] = excl + c0;
        cursor[4 * t + 2] = excl + c0 + c1;
        cursor[4 * t + 3] = excl + c0 + c1 + c2;
        if (t == 0) P0[Lc] = Lc;
        __syncthreads();

        // ---- scatter into bucket-ordered arrays ----
#pragma unroll
        for (int i = 0; i < 4; i++) {
            int pos = atomicAdd(&cursor[b[i]], 1);
            wval[pos] = v[i];
            widx[pos] = (unsigned short)(4 * t + i);
            wbkt[pos] = (unsigned short)b[i];
        }
        __syncthreads();

        // ---- exact fixup: rank within bucket by (value, index) ----
        size_t off4[4];
        float  val4[4];
#pragma unroll
        for (int i = 0; i < 4; i++) {
            int p = t + THREADS * i;
            float vv = wval[p];
            int   ii = widx[p];
            int   bb = wbkt[p];
            int start = P0[bb];
            int end   = P0[bb + 1];
            int r = p;                         // len==1 -> p == start
            if (end - start > 1) {
                r = start;
                for (int j = start; j < end; j++) {
                    float vj = wval[j];
                    if (vj < vv || (vj == vv && widx[j] < ii)) r++;
                }
            }
            if (phase == 0) {
                qv[r] = vv;
                qi[r] = (unsigned short)ii;
            } else {
                float dq = qv[r] - vv;
                val4[i]  = __expf(-dq * dq) * inv_D;
                off4[i]  = ((size_t)qi[r] << 10) | (unsigned)ii;
            }
        }

        if (phase == 1) {
            // batched independent mask probes (MLP=4), then predicated REDGs
            int m0 = mrow[off4[0]];
            int m1 = mrow[off4[1]];
            int m2 = mrow[off4[2]];
            int m3 = mrow[off4[3]];
            if (m0 == 0) atomicAdd(orow + off4[0], val4[0]);
            if (m1 == 0) atomicAdd(orow + off4[1], val4[1]);
            if (m2 == 0) atomicAdd(orow + off4[2], val4[2]);
            if (m3 == 0) atomicAdd(orow + off4[3], val4[3]);
        }
        __syncthreads();   // qv/qi complete before k-phase; arrays reused
    }
}

extern "C" void kernel_launch(void* const* d_in, const int* in_sizes, int n_in,
                              void* d_out, int out_size)
{
    const float* q    = (const float*)d_in[0];
    const float* k    = (const float*)d_in[1];
    const int*   mask = (const int*)d_in[2];
    float*       out  = (float*)d_out;

    prep_kernel<<<NCOL, THREADS>>>(q, k, out);
    sort_scatter_kernel<<<NCOL, THREADS>>>(mask, out);
}